// round 12
// baseline (speedup 1.0000x reference)
#include <cuda_runtime.h>
#include <cuda_fp16.h>
#include <math.h>

#define NN 50000
#define EE 800000
#define NSPEC 10

// ---- scratch (static device globals; allocation-free) ----
__device__ __half g_SV[NN * 256];       // packed fp16 up-projected feats [N][32][8]:
                                        //   (s0,s1,v0x,v0y,v0z,v1x,v1y,v1z) per lane
__device__ float g_A[NN * 256];         // packed aggregation [N][64][4] = (s,vx,vy,vz)
__device__ int   g_cnt[16];             // per-species node counts
__device__ int   g_bkt[NSPEC * NN];     // per-species node lists

// ============================================================================
// Species bucketing (warp-aggregated)
// ============================================================================
__global__ void k_zero_cnt() { if (threadIdx.x < 16) g_cnt[threadIdx.x] = 0; }

__global__ __launch_bounds__(256) void k_bucket(const int* __restrict__ specie, int N)
{
    int i = blockIdx.x * blockDim.x + threadIdx.x;
    if (i < N) {
        int sp = specie[i];
        unsigned mask = __match_any_sync(__activemask(), sp);
        int lane = threadIdx.x & 31;
        int leader = __ffs(mask) - 1;
        int rank = __popc(mask & ((1u << lane) - 1));
        int base = 0;
        if (lane == leader) base = atomicAdd(&g_cnt[sp], __popc(mask));
        base = __shfl_sync(mask, base, leader);
        g_bkt[sp * NN + base + rank] = i;
    }
}

// ============================================================================
// Kernel A: linear-up -> packed fp16 g_SV + zero aggregation buffer.
// ============================================================================
__global__ __launch_bounds__(256) void k_up(
    const float* __restrict__ nfs, const float* __restrict__ nfv,
    const float* __restrict__ Wus, const float* __restrict__ Wuv, int N)
{
    extern __shared__ float su[];
    float4* wsv4 = (float4*)su;
    float*  s_in = su + 8192;
    float4* v_in = (float4*)(su + 8192 + 2048);

    int tid = threadIdx.x;
    const float2* us2 = (const float2*)Wus;
    const float2* uv2 = (const float2*)Wuv;
    for (int i = tid; i < 2048; i += 256) {
        float2 a = us2[i], b = uv2[i];
        wsv4[i] = make_float4(a.x, b.x, a.y, b.y);
    }
    __syncthreads();

    int warp = tid >> 5, lane = tid & 31;
    float*  ss = s_in + warp * 256;
    float4* vv = v_in + warp * 256;

    for (int base = blockIdx.x * 32 + warp * 4; base < N; base += gridDim.x * 32) {
        int nv = N - base; if (nv > 4) nv = 4;
        #pragma unroll
        for (int j = 0; j < 4; j++) {
            if (j < nv) {
                int n = base + j;
                float2 sv = *(const float2*)(nfs + (size_t)n * 64 + 2 * lane);
                ss[j * 64 + 2 * lane]     = sv.x;
                ss[j * 64 + 2 * lane + 1] = sv.y;
                const float2* vp = (const float2*)(nfv + (size_t)n * 192);
                float2 p0 = vp[lane * 3], p1 = vp[lane * 3 + 1], p2 = vp[lane * 3 + 2];
                vv[j * 64 + 2 * lane]     = make_float4(p0.x, p0.y, p1.x, 0.f);
                vv[j * 64 + 2 * lane + 1] = make_float4(p1.y, p2.x, p2.y, 0.f);
            }
        }
        __syncwarp();

        float acc[4][8];
        #pragma unroll
        for (int j = 0; j < 4; j++)
            #pragma unroll
            for (int q = 0; q < 8; q++) acc[j][q] = 0.f;

        #pragma unroll 4
        for (int f = 0; f < 64; f++) {
            float4 wq = wsv4[f * 32 + lane];
            #pragma unroll
            for (int j = 0; j < 4; j++) {
                float  sb = ss[j * 64 + f];
                float4 vb = vv[j * 64 + f];
                acc[j][0] = fmaf(sb, wq.x, acc[j][0]);
                acc[j][1] = fmaf(sb, wq.z, acc[j][1]);
                acc[j][2] = fmaf(vb.x, wq.y, acc[j][2]);
                acc[j][3] = fmaf(vb.y, wq.y, acc[j][3]);
                acc[j][4] = fmaf(vb.z, wq.y, acc[j][4]);
                acc[j][5] = fmaf(vb.x, wq.w, acc[j][5]);
                acc[j][6] = fmaf(vb.y, wq.w, acc[j][6]);
                acc[j][7] = fmaf(vb.z, wq.w, acc[j][7]);
            }
        }

        for (int j = 0; j < nv; j++) {
            int n = base + j;
            __half2 h0 = __floats2half2_rn(acc[j][0], acc[j][1]);
            __half2 h1 = __floats2half2_rn(acc[j][2], acc[j][3]);
            __half2 h2 = __floats2half2_rn(acc[j][4], acc[j][5]);
            __half2 h3 = __floats2half2_rn(acc[j][6], acc[j][7]);
            uint4 pk;
            pk.x = *(unsigned*)&h0; pk.y = *(unsigned*)&h1;
            pk.z = *(unsigned*)&h2; pk.w = *(unsigned*)&h3;
            *((uint4*)(g_SV + (size_t)n * 256) + lane) = pk;
            float4* za = (float4*)(g_A + (size_t)n * 256);
            za[lane]      = make_float4(0.f, 0.f, 0.f, 0.f);
            za[32 + lane] = make_float4(0.f, 0.f, 0.f, 0.f);
        }
        __syncwarp();
    }
}

// ============================================================================
// Kernel B (warp-specialized pipeline, fp16 MMA): 512 threads, 2 blocks/SM.
//   warps 0-7  (producers): edge-info + radial MLP (fp16 MMA) tile t -> smem[p]
//   warps 8-15 (consumers): messages + atomic scatter tile t-1 from smem[1-p]
// fp16 sender-feature gather: ONE LDG.128 per lane per edge.
// ============================================================================
__global__ __launch_bounds__(512, 2) void k_edge(
    const float* __restrict__ RE, const float* __restrict__ Wr1,
    const float* __restrict__ Wr2, const float* __restrict__ vectors,
    const int* __restrict__ senders, const int* __restrict__ receivers, int En)
{
    extern __shared__ float sg[];
    __half* wr2t = (__half*)sg;                     // [320][72] halfs -> 11520 floats
    __half* csmH = (__half*)(sg + 11520);           // 2 * 32*328 halfs -> 10496 floats
    __half* hu   = (__half*)(sg + 22016);           // [32][72] halfs -> 1152 floats
    float*  res  = sg + 23168;                      // 256
    float*  wr1s = sg + 23424;                      // 512
    float*  einf = sg + 23936;                      // 2 * 32 * 8 = 512
    // total 24448 floats = 97792 B

    int tid = threadIdx.x;
    // stage W_r2 transposed: wr2t[n][j] = Wr2[j][n]
    for (int i = tid; i < 20480; i += 512) {
        int j = i / 320, n = i - j * 320;
        wr2t[n * 72 + j] = __float2half_rn(Wr2[i]);
    }
    for (int i = tid; i < 512; i += 512) wr1s[i] = Wr1[i];
    __syncthreads();

    int lane = tid & 31, warp = tid >> 5;
    int gid = lane >> 2, tig = lane & 3;
    bool producer = (warp < 8);
    int ntiles = (En + 31) >> 5;
    int gd = gridDim.x;
    int p = 0;

    // producer-persistent Wr1 registers (j fixed per thread across all tiles)
    int jj = (tid & 31) * 2;
    float2 w1r[8];
    if (producer) {
        #pragma unroll
        for (int k = 0; k < 8; k++)
            w1r[k] = *(const float2*)(wr1s + k * 64 + jj);
    }

    for (int it = 0; ; it++) {
        int tP = blockIdx.x + it * gd;
        int tC = tP - gd;
        if (tC >= ntiles) break;
        __half* bufP = csmH + p * 10496;
        __half* bufC = csmH + (1 - p) * 10496;

        if (producer && tP < ntiles) {
            int e0 = tP << 5;
            // stage RE tile + per-edge info (Y, s, r)
            {
                int el = tid >> 3;
                int e = e0 + el;
                res[tid] = (e < En) ? __ldg(RE + (size_t)e * 8 + (tid & 7)) : 0.f;
                if (tid < 32) {
                    int ee = e0 + tid;
                    float* ei = einf + p * 256 + tid * 8;
                    if (ee < En) {
                        float vx = __ldg(vectors + (size_t)ee * 3 + 0);
                        float vy = __ldg(vectors + (size_t)ee * 3 + 1);
                        float vz = __ldg(vectors + (size_t)ee * 3 + 2);
                        float ri = 1.f / (sqrtf(vx * vx + vy * vy + vz * vz) + 1e-9f);
                        ei[0] = vx * ri; ei[1] = vy * ri; ei[2] = vz * ri;
                        ei[3] = __int_as_float(__ldg(senders + ee));
                        ei[4] = __int_as_float(__ldg(receivers + ee));
                    }
                }
            }
            asm volatile("bar.sync 1, 256;" ::: "memory");
            // h = silu(res @ W_r1); Wr1 already in registers
            #pragma unroll
            for (int i = 0; i < 4; i++) {
                int e = (tid >> 5) + 8 * i;
                const float* rr = res + e * 8;
                float a0 = 0.f, a1 = 0.f;
                #pragma unroll
                for (int k = 0; k < 8; k++) {
                    float r = rr[k];
                    a0 = fmaf(r, w1r[k].x, a0);
                    a1 = fmaf(r, w1r[k].y, a1);
                }
                float h0 = __fdividef(a0, 1.f + __expf(-a0));
                float h1 = __fdividef(a1, 1.f + __expf(-a1));
                *(half2*)(hu + e * 72 + jj) = __floats2half2_rn(h0, h1);
            }
            asm volatile("bar.sync 1, 256;" ::: "memory");

            // MMA: C[32,320] = h @ W_r2 (fp16 in, fp32 accum), warp = 40-col strip
            float c[2][5][4];
            #pragma unroll
            for (int mt = 0; mt < 2; mt++)
                #pragma unroll
                for (int nt = 0; nt < 5; nt++)
                    #pragma unroll
                    for (int q = 0; q < 4; q++) c[mt][nt][q] = 0.f;

            #pragma unroll
            for (int ks = 0; ks < 4; ks++) {
                int kb = ks * 16;
                unsigned a[2][4];
                #pragma unroll
                for (int mt = 0; mt < 2; mt++) {
                    int r0 = mt * 16 + gid;
                    a[mt][0] = *(const unsigned*)(hu + r0 * 72 + kb + 2 * tig);
                    a[mt][1] = *(const unsigned*)(hu + (r0 + 8) * 72 + kb + 2 * tig);
                    a[mt][2] = *(const unsigned*)(hu + r0 * 72 + kb + 2 * tig + 8);
                    a[mt][3] = *(const unsigned*)(hu + (r0 + 8) * 72 + kb + 2 * tig + 8);
                }
                #pragma unroll
                for (int nt = 0; nt < 5; nt++) {
                    int col = warp * 40 + nt * 8 + gid;
                    unsigned b0 = *(const unsigned*)(wr2t + col * 72 + kb + 2 * tig);
                    unsigned b1 = *(const unsigned*)(wr2t + col * 72 + kb + 2 * tig + 8);
                    #pragma unroll
                    for (int mt = 0; mt < 2; mt++) {
                        asm volatile(
                            "mma.sync.aligned.m16n8k16.row.col.f32.f16.f16.f32 "
                            "{%0,%1,%2,%3}, {%4,%5,%6,%7}, {%8,%9}, {%0,%1,%2,%3};\n"
                            : "+f"(c[mt][nt][0]), "+f"(c[mt][nt][1]),
                              "+f"(c[mt][nt][2]), "+f"(c[mt][nt][3])
                            : "r"(a[mt][0]), "r"(a[mt][1]), "r"(a[mt][2]), "r"(a[mt][3]),
                              "r"(b0), "r"(b1));
                    }
                }
            }
            // store C fragments into bufP as fp16
            #pragma unroll
            for (int mt = 0; mt < 2; mt++) {
                int r0 = mt * 16 + gid;
                #pragma unroll
                for (int nt = 0; nt < 5; nt++) {
                    int col = warp * 40 + nt * 8 + 2 * tig;
                    *(half2*)(bufP + r0 * 328 + col) =
                        __floats2half2_rn(c[mt][nt][0], c[mt][nt][1]);
                    *(half2*)(bufP + (r0 + 8) * 328 + col) =
                        __floats2half2_rn(c[mt][nt][2], c[mt][nt][3]);
                }
            }
        }

        if (!producer && tC >= 0) {
            int e0 = tC << 5;
            int cw = warp - 8;
            const float* einfC = einf + (1 - p) * 256;
            #pragma unroll
            for (int i = 0; i < 4; i++) {
                int el = cw * 4 + i;
                int e = e0 + el;
                if (e < En) {
                    const __half* cwp = bufC + el * 328;
                    float2 w0 = __half22float2(*(const half2*)(cwp + 2 * lane));
                    float2 w1 = __half22float2(*(const half2*)(cwp + 64 + 2 * lane));
                    float2 w2 = __half22float2(*(const half2*)(cwp + 128 + 2 * lane));
                    float2 w3 = __half22float2(*(const half2*)(cwp + 192 + 2 * lane));
                    float2 w4 = __half22float2(*(const half2*)(cwp + 256 + 2 * lane));

                    const float* ei = einfC + el * 8;
                    float Y0 = ei[0], Y1 = ei[1], Y2 = ei[2];
                    int s = __float_as_int(ei[3]);
                    int r = __float_as_int(ei[4]);

                    // single 16B gather of packed fp16 sender features
                    uint4 q = __ldg((const uint4*)(g_SV + (size_t)s * 256) + lane);
                    float2 s01 = __half22float2(*(const half2*)&q.x);
                    float2 v01 = __half22float2(*(const half2*)&q.y);
                    float2 v23 = __half22float2(*(const half2*)&q.z);
                    float2 v45 = __half22float2(*(const half2*)&q.w);
                    float xs0 = s01.x, xs1 = s01.y;
                    float a0 = v01.x, a1 = v01.y, a2 = v23.x;
                    float b0 = v23.y, b1 = v45.x, b2 = v45.y;

                    float dota = a0 * Y0 + a1 * Y1 + a2 * Y2;
                    float dotb = b0 * Y0 + b1 * Y1 + b2 * Y2;

                    float msa = w0.x * xs0 + w3.x * dota;
                    float msb = w0.y * xs1 + w3.y * dotb;

                    float cxa0 = a1 * Y2 - a2 * Y1;
                    float cxa1 = a2 * Y0 - a0 * Y2;
                    float cxa2 = a0 * Y1 - a1 * Y0;
                    float cxb0 = b1 * Y2 - b2 * Y1;
                    float cxb1 = b2 * Y0 - b0 * Y2;
                    float cxb2 = b0 * Y1 - b1 * Y0;

                    float sa = w1.x * xs0, sb = w1.y * xs1;
                    float mva0 = sa * Y0 + w2.x * a0 + w4.x * cxa0;
                    float mva1 = sa * Y1 + w2.x * a1 + w4.x * cxa1;
                    float mva2 = sa * Y2 + w2.x * a2 + w4.x * cxa2;
                    float mvb0 = sb * Y0 + w2.y * b0 + w4.y * cxb0;
                    float mvb1 = sb * Y1 + w2.y * b1 + w4.y * cxb1;
                    float mvb2 = sb * Y2 + w2.y * b2 + w4.y * cxb2;

                    float* base = g_A + (size_t)r * 256 + lane * 8;
                    asm volatile("red.global.add.v4.f32 [%0], {%1,%2,%3,%4};"
                                 :: "l"(base), "f"(msa), "f"(mva0), "f"(mva1), "f"(mva2)
                                 : "memory");
                    asm volatile("red.global.add.v4.f32 [%0], {%1,%2,%3,%4};"
                                 :: "l"(base + 4), "f"(msb), "f"(mvb0), "f"(mvb1), "f"(mvb2)
                                 : "memory");
                }
            }
        }
        __syncthreads();
        p ^= 1;
    }
}

// ============================================================================
// Kernel C: node post. Blocks own ONE species (skip weights staged in smem).
// ============================================================================
__global__ __launch_bounds__(256) void k_node(
    const float* __restrict__ nfs, const float* __restrict__ nfv,
    const float* __restrict__ Wds, const float* __restrict__ Wdv,
    const float* __restrict__ wsym_s, const float* __restrict__ wsym_v,
    const float* __restrict__ WLs, const float* __restrict__ WLv,
    const float* __restrict__ Wsk_s, const float* __restrict__ Wsk_v,
    const float* __restrict__ Wout,
    float* __restrict__ out0, float* __restrict__ fsO, float* __restrict__ fvO)
{
    extern __shared__ float sn[];
    float4* wd4  = (float4*)sn;
    float4* wl4  = (float4*)(sn + 8192);
    float4* sk4  = (float4*)(sn + 16384);
    float*  wsym = sn + 24576;
    float*  wout = sn + 24896;
    float4* aggb = (float4*)(sn + 24960);
    float4* nfb  = (float4*)(sn + 24960 + 8192);
    float4* psb  = (float4*)(sn + 24960 + 16384);

    int tid = threadIdx.x;
    int sp = blockIdx.y;

    {
        const float2* ds2 = (const float2*)Wds;
        const float2* dv2 = (const float2*)Wdv;
        const float2* ls2 = (const float2*)WLs;
        const float2* lv2 = (const float2*)WLv;
        const float2* ss2 = (const float2*)(Wsk_s + (size_t)sp * 4096);
        const float2* sv2 = (const float2*)(Wsk_v + (size_t)sp * 4096);
        for (int i = tid; i < 2048; i += 256) {
            float2 a = ds2[i], b = dv2[i];
            wd4[i] = make_float4(a.x, b.x, a.y, b.y);
            float2 cl = ls2[i], dl = lv2[i];
            wl4[i] = make_float4(cl.x, dl.x, cl.y, dl.y);
            float2 e = ss2[i], f = sv2[i];
            sk4[i] = make_float4(e.x, f.x, e.y, f.y);
        }
        for (int i = tid; i < 192; i += 256) wsym[i] = wsym_s[sp * 192 + i];
        for (int i = tid; i < 128; i += 256) wsym[192 + i] = wsym_v[sp * 128 + i];
        if (tid < 64) wout[tid] = Wout[tid];
    }
    __syncthreads();

    int warp = tid >> 5, lane = tid & 31;
    float4* ab = aggb + warp * 256;
    float4* nb = nfb + warp * 256;
    float4* pb = psb + warp * 256;
    int cnt = g_cnt[sp];
    const int* lst = g_bkt + sp * NN;
    const float* ws0 = wsym, *ws1 = wsym + 64, *ws2 = wsym + 128;
    const float* wv0 = wsym + 192, *wv1 = wsym + 256;

    for (int base = blockIdx.x * 32 + warp * 4; base < cnt; base += gridDim.x * 32) {
        int nv = cnt - base; if (nv > 4) nv = 4;
        int nn[4];
        #pragma unroll
        for (int j = 0; j < 4; j++) nn[j] = lst[base + ((j < nv) ? j : 0)];

        #pragma unroll
        for (int j = 0; j < 4; j++) {
            int n = nn[j];
            const float4* ga = (const float4*)g_A + (size_t)n * 64;
            ab[j * 64 + 2 * lane]     = ga[2 * lane];
            ab[j * 64 + 2 * lane + 1] = ga[2 * lane + 1];
            float2 sv = *(const float2*)(nfs + (size_t)n * 64 + 2 * lane);
            const float2* vp = (const float2*)(nfv + (size_t)n * 192);
            float2 p0 = vp[lane * 3], p1 = vp[lane * 3 + 1], p2 = vp[lane * 3 + 2];
            nb[j * 64 + 2 * lane]     = make_float4(sv.x, p0.x, p0.y, p1.x);
            nb[j * 64 + 2 * lane + 1] = make_float4(sv.y, p1.y, p2.x, p2.y);
        }
        __syncwarp();

        float acc[4][8];
        #pragma unroll
        for (int j = 0; j < 4; j++)
            #pragma unroll
            for (int q = 0; q < 8; q++) acc[j][q] = 0.f;

        #pragma unroll 4
        for (int f = 0; f < 64; f++) {
            float4 wq = wd4[f * 32 + lane];
            #pragma unroll
            for (int j = 0; j < 4; j++) {
                float4 a = ab[j * 64 + f];
                acc[j][0] = fmaf(a.x, wq.x, acc[j][0]);
                acc[j][1] = fmaf(a.y, wq.y, acc[j][1]);
                acc[j][2] = fmaf(a.z, wq.y, acc[j][2]);
                acc[j][3] = fmaf(a.w, wq.y, acc[j][3]);
                acc[j][4] = fmaf(a.x, wq.z, acc[j][4]);
                acc[j][5] = fmaf(a.y, wq.w, acc[j][5]);
                acc[j][6] = fmaf(a.z, wq.w, acc[j][6]);
                acc[j][7] = fmaf(a.w, wq.w, acc[j][7]);
            }
        }

        int c0 = 2 * lane, c1 = 2 * lane + 1;
        #pragma unroll
        for (int j = 0; j < 4; j++) {
            float sa0 = acc[j][0] * 0.25f, va0 = acc[j][1] * 0.25f;
            float va1 = acc[j][2] * 0.25f, va2 = acc[j][3] * 0.25f;
            float sa1 = acc[j][4] * 0.25f, vb0 = acc[j][5] * 0.25f;
            float vb1 = acc[j][6] * 0.25f, vb2 = acc[j][7] * 0.25f;
            float ps0 = ws0[c0] * sa0 + ws1[c0] * sa0 * sa0
                      + ws2[c0] * (va0 * va0 + va1 * va1 + va2 * va2);
            float cc0 = wv0[c0] + wv1[c0] * sa0;
            float ps1 = ws0[c1] * sa1 + ws1[c1] * sa1 * sa1
                      + ws2[c1] * (vb0 * vb0 + vb1 * vb1 + vb2 * vb2);
            float cc1 = wv0[c1] + wv1[c1] * sa1;
            pb[j * 64 + c0] = make_float4(ps0, cc0 * va0, cc0 * va1, cc0 * va2);
            pb[j * 64 + c1] = make_float4(ps1, cc1 * vb0, cc1 * vb1, cc1 * vb2);
        }
        __syncwarp();

        float a2c[4][8];
        #pragma unroll
        for (int j = 0; j < 4; j++)
            #pragma unroll
            for (int q = 0; q < 8; q++) a2c[j][q] = 0.f;

        #pragma unroll 4
        for (int f = 0; f < 64; f++) {
            float4 wl = wl4[f * 32 + lane];
            float4 sk = sk4[f * 32 + lane];
            #pragma unroll
            for (int j = 0; j < 4; j++) {
                float4 p = pb[j * 64 + f];
                float4 q = nb[j * 64 + f];
                a2c[j][0] = fmaf(p.x, wl.x, fmaf(q.x, sk.x, a2c[j][0]));
                a2c[j][1] = fmaf(p.y, wl.y, fmaf(q.y, sk.y, a2c[j][1]));
                a2c[j][2] = fmaf(p.z, wl.y, fmaf(q.z, sk.y, a2c[j][2]));
                a2c[j][3] = fmaf(p.w, wl.y, fmaf(q.w, sk.y, a2c[j][3]));
                a2c[j][4] = fmaf(p.x, wl.z, fmaf(q.x, sk.z, a2c[j][4]));
                a2c[j][5] = fmaf(p.y, wl.w, fmaf(q.y, sk.w, a2c[j][5]));
                a2c[j][6] = fmaf(p.z, wl.w, fmaf(q.z, sk.w, a2c[j][6]));
                a2c[j][7] = fmaf(p.w, wl.w, fmaf(q.w, sk.w, a2c[j][7]));
            }
        }

        #pragma unroll
        for (int j = 0; j < 4; j++) {
            int n = nn[j];
            float r = a2c[j][0] * wout[c0] + a2c[j][4] * wout[c1];
            #pragma unroll
            for (int off = 16; off > 0; off >>= 1)
                r += __shfl_xor_sync(0xffffffffu, r, off);
            if (j < nv) {
                *(float2*)(fsO + (size_t)n * 64 + c0) = make_float2(a2c[j][0], a2c[j][4]);
                float* vb = fvO + (size_t)n * 192 + 6 * lane;
                *(float2*)(vb)     = make_float2(a2c[j][1], a2c[j][2]);
                *(float2*)(vb + 2) = make_float2(a2c[j][3], a2c[j][5]);
                *(float2*)(vb + 4) = make_float2(a2c[j][6], a2c[j][7]);
                if (lane == 0) out0[n] = r;
            }
        }
        __syncwarp();
    }
}

// ============================================================================
extern "C" void kernel_launch(void* const* d_in, const int* in_sizes, int n_in,
                              void* d_out, int out_size)
{
    const float* vectors  = (const float*)d_in[0];
    const float* nfs      = (const float*)d_in[1];
    const float* nfv      = (const float*)d_in[2];
    const float* RE       = (const float*)d_in[3];
    const float* Wus      = (const float*)d_in[4];
    const float* Wuv      = (const float*)d_in[5];
    const float* Wr1      = (const float*)d_in[6];
    const float* Wr2      = (const float*)d_in[7];
    const float* Wds      = (const float*)d_in[8];
    const float* Wdv      = (const float*)d_in[9];
    const float* wsym_s   = (const float*)d_in[10];
    const float* wsym_v   = (const float*)d_in[11];
    const float* WLs      = (const float*)d_in[12];
    const float* WLv      = (const float*)d_in[13];
    const float* Wsk_s    = (const float*)d_in[14];
    const float* Wsk_v    = (const float*)d_in[15];
    const float* Wout     = (const float*)d_in[16];
    const int*   specie   = (const int*)d_in[17];
    const int*   senders  = (const int*)d_in[18];
    const int*   receivers= (const int*)d_in[19];

    int N = in_sizes[1] / 64;
    int E = in_sizes[18];
    if (N > NN) N = NN;
    if (E > EE) E = EE;

    float* out0 = (float*)d_out;
    float* fsO  = out0 + N;
    float* fvO  = fsO + (size_t)N * 64;

    const int UP_SMEM   = (8192 + 2048 + 8192) * 4;                 // 73728 B
    const int EDGE_SMEM = 24448 * 4;                                // 97792 B
    const int NODE_SMEM = (24960 + 3 * 8192) * 4;                   // 198144 B
    cudaFuncSetAttribute(k_up,   cudaFuncAttributeMaxDynamicSharedMemorySize, UP_SMEM);
    cudaFuncSetAttribute(k_edge, cudaFuncAttributeMaxDynamicSharedMemorySize, EDGE_SMEM);
    cudaFuncSetAttribute(k_node, cudaFuncAttributeMaxDynamicSharedMemorySize, NODE_SMEM);

    // species bucketing
    k_zero_cnt<<<1, 32>>>();
    k_bucket<<<(N + 255) / 256, 256>>>(specie, N);

    k_up<<<296, 256, UP_SMEM>>>(nfs, nfv, Wus, Wuv, N);
    k_edge<<<296, 512, EDGE_SMEM>>>(RE, Wr1, Wr2, vectors, senders, receivers, E);
    k_node<<<dim3(15, NSPEC), 256, NODE_SMEM>>>(nfs, nfv, Wds, Wdv,
                                                wsym_s, wsym_v, WLs, WLv,
                                                Wsk_s, Wsk_v, Wout,
                                                out0, fsO, fvO);
}

// round 16
// speedup vs baseline: 1.5877x; 1.5877x over previous
#include <cuda_runtime.h>
#include <cuda_fp16.h>
#include <math.h>

#define NN 50000
#define EE 800000
#define NSPEC 10

// ---- scratch (static device globals; allocation-free) ----
__device__ float g_SV[NN * 256];        // packed fp32 up-projected feats [N][32][8]:
                                        //   (s0,s1,v0x,v0y | v0z,v1x,v1y,v1z)
__device__ float g_A[NN * 256];         // aggregation [N][2][32][4]:
                                        //   block0 = channel 2l (s,vx,vy,vz), block1 = channel 2l+1
__device__ int   g_cnt[16];             // per-species node counts
__device__ int   g_bkt[NSPEC * NN];     // per-species node lists

// ============================================================================
// Species bucketing (warp-aggregated)
// ============================================================================
__global__ void k_zero_cnt() { if (threadIdx.x < 16) g_cnt[threadIdx.x] = 0; }

__global__ __launch_bounds__(256) void k_bucket(const int* __restrict__ specie, int N)
{
    int i = blockIdx.x * blockDim.x + threadIdx.x;
    if (i < N) {
        int sp = specie[i];
        unsigned mask = __match_any_sync(__activemask(), sp);
        int lane = threadIdx.x & 31;
        int leader = __ffs(mask) - 1;
        int rank = __popc(mask & ((1u << lane) - 1));
        int base = 0;
        if (lane == leader) base = atomicAdd(&g_cnt[sp], __popc(mask));
        base = __shfl_sync(mask, base, leader);
        g_bkt[sp * NN + base + rank] = i;
    }
}

// ============================================================================
// Kernel A: linear-up -> packed g_SV + zero aggregation buffer.
// ============================================================================
__global__ __launch_bounds__(256) void k_up(
    const float* __restrict__ nfs, const float* __restrict__ nfv,
    const float* __restrict__ Wus, const float* __restrict__ Wuv, int N)
{
    extern __shared__ float su[];
    float4* wsv4 = (float4*)su;
    float*  s_in = su + 8192;
    float4* v_in = (float4*)(su + 8192 + 2048);

    int tid = threadIdx.x;
    const float2* us2 = (const float2*)Wus;
    const float2* uv2 = (const float2*)Wuv;
    for (int i = tid; i < 2048; i += 256) {
        float2 a = us2[i], b = uv2[i];
        wsv4[i] = make_float4(a.x, b.x, a.y, b.y);
    }
    __syncthreads();

    int warp = tid >> 5, lane = tid & 31;
    float*  ss = s_in + warp * 256;
    float4* vv = v_in + warp * 256;

    for (int base = blockIdx.x * 32 + warp * 4; base < N; base += gridDim.x * 32) {
        int nv = N - base; if (nv > 4) nv = 4;
        #pragma unroll
        for (int j = 0; j < 4; j++) {
            if (j < nv) {
                int n = base + j;
                float2 sv = *(const float2*)(nfs + (size_t)n * 64 + 2 * lane);
                ss[j * 64 + 2 * lane]     = sv.x;
                ss[j * 64 + 2 * lane + 1] = sv.y;
                const float2* vp = (const float2*)(nfv + (size_t)n * 192);
                float2 p0 = vp[lane * 3], p1 = vp[lane * 3 + 1], p2 = vp[lane * 3 + 2];
                vv[j * 64 + 2 * lane]     = make_float4(p0.x, p0.y, p1.x, 0.f);
                vv[j * 64 + 2 * lane + 1] = make_float4(p1.y, p2.x, p2.y, 0.f);
            }
        }
        __syncwarp();

        float acc[4][8];
        #pragma unroll
        for (int j = 0; j < 4; j++)
            #pragma unroll
            for (int q = 0; q < 8; q++) acc[j][q] = 0.f;

        #pragma unroll 4
        for (int f = 0; f < 64; f++) {
            float4 wq = wsv4[f * 32 + lane];
            #pragma unroll
            for (int j = 0; j < 4; j++) {
                float  sb = ss[j * 64 + f];
                float4 vb = vv[j * 64 + f];
                acc[j][0] = fmaf(sb, wq.x, acc[j][0]);
                acc[j][1] = fmaf(sb, wq.z, acc[j][1]);
                acc[j][2] = fmaf(vb.x, wq.y, acc[j][2]);
                acc[j][3] = fmaf(vb.y, wq.y, acc[j][3]);
                acc[j][4] = fmaf(vb.z, wq.y, acc[j][4]);
                acc[j][5] = fmaf(vb.x, wq.w, acc[j][5]);
                acc[j][6] = fmaf(vb.y, wq.w, acc[j][6]);
                acc[j][7] = fmaf(vb.z, wq.w, acc[j][7]);
            }
        }

        for (int j = 0; j < nv; j++) {
            int n = base + j;
            float4* gp = (float4*)(g_SV + (size_t)n * 256) + lane * 2;
            gp[0] = make_float4(acc[j][0], acc[j][1], acc[j][2], acc[j][3]);
            gp[1] = make_float4(acc[j][4], acc[j][5], acc[j][6], acc[j][7]);
            float4* za = (float4*)(g_A + (size_t)n * 256);
            za[lane]      = make_float4(0.f, 0.f, 0.f, 0.f);
            za[32 + lane] = make_float4(0.f, 0.f, 0.f, 0.f);
        }
        __syncwarp();
    }
}

// ============================================================================
// Kernel B (warp-specialized pipeline, fp16 MMA): 512 threads, 2 blocks/SM.
//   warps 0-7  (producers): edge-info + radial MLP (fp16 MMA) tile t -> smem[p]
//   warps 8-15 (consumers): messages + atomic scatter tile t-1 from smem[1-p]
// Aggregation REDs use the split [2][32][4] layout: each red.v4 covers a
// contiguous 512B span -> 4 L1 wavefronts instead of 8.
// ============================================================================
__global__ __launch_bounds__(512, 2) void k_edge(
    const float* __restrict__ RE, const float* __restrict__ Wr1,
    const float* __restrict__ Wr2, const float* __restrict__ vectors,
    const int* __restrict__ senders, const int* __restrict__ receivers, int En)
{
    extern __shared__ float sg[];
    __half* wr2t = (__half*)sg;                     // [320][72] halfs -> 11520 floats
    __half* csmH = (__half*)(sg + 11520);           // 2 * 32*328 halfs -> 10496 floats
    __half* hu   = (__half*)(sg + 22016);           // [32][72] halfs -> 1152 floats
    float*  res  = sg + 23168;                      // 256
    float*  wr1s = sg + 23424;                      // 512
    float*  einf = sg + 23936;                      // 2 * 32 * 8 = 512
    // total 24448 floats = 97792 B

    int tid = threadIdx.x;
    // stage W_r2 transposed: wr2t[n][j] = Wr2[j][n]
    for (int i = tid; i < 20480; i += 512) {
        int j = i / 320, n = i - j * 320;
        wr2t[n * 72 + j] = __float2half_rn(Wr2[i]);
    }
    for (int i = tid; i < 512; i += 512) wr1s[i] = Wr1[i];
    __syncthreads();

    int lane = tid & 31, warp = tid >> 5;
    int gid = lane >> 2, tig = lane & 3;
    bool producer = (warp < 8);
    int ntiles = (En + 31) >> 5;
    int gd = gridDim.x;
    int p = 0;

    for (int it = 0; ; it++) {
        int tP = blockIdx.x + it * gd;
        int tC = tP - gd;
        if (tC >= ntiles) break;
        __half* bufP = csmH + p * 10496;
        __half* bufC = csmH + (1 - p) * 10496;

        if (producer && tP < ntiles) {
            int e0 = tP << 5;
            // stage RE tile + per-edge info (Y, s, r)
            {
                int el = tid >> 3;
                int e = e0 + el;
                res[tid] = (e < En) ? __ldg(RE + (size_t)e * 8 + (tid & 7)) : 0.f;
                if (tid < 32) {
                    int ee = e0 + tid;
                    float* ei = einf + p * 256 + tid * 8;
                    if (ee < En) {
                        float vx = __ldg(vectors + (size_t)ee * 3 + 0);
                        float vy = __ldg(vectors + (size_t)ee * 3 + 1);
                        float vz = __ldg(vectors + (size_t)ee * 3 + 2);
                        float ri = 1.f / (sqrtf(vx * vx + vy * vy + vz * vz) + 1e-9f);
                        ei[0] = vx * ri; ei[1] = vy * ri; ei[2] = vz * ri;
                        ei[3] = __int_as_float(__ldg(senders + ee));
                        ei[4] = __int_as_float(__ldg(receivers + ee));
                    }
                }
            }
            asm volatile("bar.sync 1, 256;" ::: "memory");
            // h = silu(res @ W_r1), two adjacent j per thread -> half2 store
            #pragma unroll
            for (int i = 0; i < 4; i++) {
                int idx = tid + 256 * i;        // 0..1023
                int e = idx >> 5;               // 0..31
                int j = (idx & 31) * 2;         // 0..62 even
                const float* rr = res + e * 8;
                float a0 = 0.f, a1 = 0.f;
                #pragma unroll
                for (int k = 0; k < 8; k++) {
                    float r = rr[k];
                    a0 = fmaf(r, wr1s[k * 64 + j], a0);
                    a1 = fmaf(r, wr1s[k * 64 + j + 1], a1);
                }
                float h0 = __fdividef(a0, 1.f + __expf(-a0));
                float h1 = __fdividef(a1, 1.f + __expf(-a1));
                *(half2*)(hu + e * 72 + j) = __floats2half2_rn(h0, h1);
            }
            asm volatile("bar.sync 1, 256;" ::: "memory");

            // MMA: C[32,320] = h @ W_r2 (fp16 in, fp32 accum), warp = 40-col strip
            float c[2][5][4];
            #pragma unroll
            for (int mt = 0; mt < 2; mt++)
                #pragma unroll
                for (int nt = 0; nt < 5; nt++)
                    #pragma unroll
                    for (int q = 0; q < 4; q++) c[mt][nt][q] = 0.f;

            #pragma unroll
            for (int ks = 0; ks < 4; ks++) {
                int kb = ks * 16;
                unsigned a[2][4];
                #pragma unroll
                for (int mt = 0; mt < 2; mt++) {
                    int r0 = mt * 16 + gid;
                    a[mt][0] = *(const unsigned*)(hu + r0 * 72 + kb + 2 * tig);
                    a[mt][1] = *(const unsigned*)(hu + (r0 + 8) * 72 + kb + 2 * tig);
                    a[mt][2] = *(const unsigned*)(hu + r0 * 72 + kb + 2 * tig + 8);
                    a[mt][3] = *(const unsigned*)(hu + (r0 + 8) * 72 + kb + 2 * tig + 8);
                }
                #pragma unroll
                for (int nt = 0; nt < 5; nt++) {
                    int col = warp * 40 + nt * 8 + gid;
                    unsigned b0 = *(const unsigned*)(wr2t + col * 72 + kb + 2 * tig);
                    unsigned b1 = *(const unsigned*)(wr2t + col * 72 + kb + 2 * tig + 8);
                    #pragma unroll
                    for (int mt = 0; mt < 2; mt++) {
                        asm volatile(
                            "mma.sync.aligned.m16n8k16.row.col.f32.f16.f16.f32 "
                            "{%0,%1,%2,%3}, {%4,%5,%6,%7}, {%8,%9}, {%0,%1,%2,%3};\n"
                            : "+f"(c[mt][nt][0]), "+f"(c[mt][nt][1]),
                              "+f"(c[mt][nt][2]), "+f"(c[mt][nt][3])
                            : "r"(a[mt][0]), "r"(a[mt][1]), "r"(a[mt][2]), "r"(a[mt][3]),
                              "r"(b0), "r"(b1));
                    }
                }
            }
            // store C fragments into bufP as fp16
            #pragma unroll
            for (int mt = 0; mt < 2; mt++) {
                int r0 = mt * 16 + gid;
                #pragma unroll
                for (int nt = 0; nt < 5; nt++) {
                    int col = warp * 40 + nt * 8 + 2 * tig;
                    *(half2*)(bufP + r0 * 328 + col) =
                        __floats2half2_rn(c[mt][nt][0], c[mt][nt][1]);
                    *(half2*)(bufP + (r0 + 8) * 328 + col) =
                        __floats2half2_rn(c[mt][nt][2], c[mt][nt][3]);
                }
            }
        }

        if (!producer && tC >= 0) {
            int e0 = tC << 5;
            int cw = warp - 8;
            const float* einfC = einf + (1 - p) * 256;
            #pragma unroll
            for (int i = 0; i < 4; i++) {
                int el = cw * 4 + i;
                int e = e0 + el;
                if (e < En) {
                    const __half* cwp = bufC + el * 328;
                    float2 w0 = __half22float2(*(const half2*)(cwp + 2 * lane));
                    float2 w1 = __half22float2(*(const half2*)(cwp + 64 + 2 * lane));
                    float2 w2 = __half22float2(*(const half2*)(cwp + 128 + 2 * lane));
                    float2 w3 = __half22float2(*(const half2*)(cwp + 192 + 2 * lane));
                    float2 w4 = __half22float2(*(const half2*)(cwp + 256 + 2 * lane));

                    const float* ei = einfC + el * 8;
                    float Y0 = ei[0], Y1 = ei[1], Y2 = ei[2];
                    int s = __float_as_int(ei[3]);
                    int r = __float_as_int(ei[4]);

                    const float4* gp = (const float4*)(g_SV + (size_t)s * 256) + lane * 2;
                    float4 q1 = __ldg(gp);
                    float4 q2 = __ldg(gp + 1);
                    float xs0 = q1.x, xs1 = q1.y;
                    float a0 = q1.z, a1 = q1.w, a2 = q2.x;
                    float b0 = q2.y, b1 = q2.z, b2 = q2.w;

                    float dota = a0 * Y0 + a1 * Y1 + a2 * Y2;
                    float dotb = b0 * Y0 + b1 * Y1 + b2 * Y2;

                    float msa = w0.x * xs0 + w3.x * dota;
                    float msb = w0.y * xs1 + w3.y * dotb;

                    float cxa0 = a1 * Y2 - a2 * Y1;
                    float cxa1 = a2 * Y0 - a0 * Y2;
                    float cxa2 = a0 * Y1 - a1 * Y0;
                    float cxb0 = b1 * Y2 - b2 * Y1;
                    float cxb1 = b2 * Y0 - b0 * Y2;
                    float cxb2 = b0 * Y1 - b1 * Y0;

                    float sa = w1.x * xs0, sb = w1.y * xs1;
                    float mva0 = sa * Y0 + w2.x * a0 + w4.x * cxa0;
                    float mva1 = sa * Y1 + w2.x * a1 + w4.x * cxa1;
                    float mva2 = sa * Y2 + w2.x * a2 + w4.x * cxa2;
                    float mvb0 = sb * Y0 + w2.y * b0 + w4.y * cxb0;
                    float mvb1 = sb * Y1 + w2.y * b1 + w4.y * cxb1;
                    float mvb2 = sb * Y2 + w2.y * b2 + w4.y * cxb2;

                    // split layout: channel-2l block then channel-2l+1 block,
                    // each red.v4 spans a contiguous 512B across the warp
                    float* baseA = g_A + (size_t)r * 256 + lane * 4;
                    asm volatile("red.global.add.v4.f32 [%0], {%1,%2,%3,%4};"
                                 :: "l"(baseA), "f"(msa), "f"(mva0), "f"(mva1), "f"(mva2)
                                 : "memory");
                    asm volatile("red.global.add.v4.f32 [%0], {%1,%2,%3,%4};"
                                 :: "l"(baseA + 128), "f"(msb), "f"(mvb0), "f"(mvb1), "f"(mvb2)
                                 : "memory");
                }
            }
        }
        __syncthreads();
        p ^= 1;
    }
}

// ============================================================================
// Kernel C: node post. Blocks own ONE species (skip weights staged in smem).
// Reads g_A in the split [2][32][4] layout.
// ============================================================================
__global__ __launch_bounds__(256) void k_node(
    const float* __restrict__ nfs, const float* __restrict__ nfv,
    const float* __restrict__ Wds, const float* __restrict__ Wdv,
    const float* __restrict__ wsym_s, const float* __restrict__ wsym_v,
    const float* __restrict__ WLs, const float* __restrict__ WLv,
    const float* __restrict__ Wsk_s, const float* __restrict__ Wsk_v,
    const float* __restrict__ Wout,
    float* __restrict__ out0, float* __restrict__ fsO, float* __restrict__ fvO)
{
    extern __shared__ float sn[];
    float4* wd4  = (float4*)sn;
    float4* wl4  = (float4*)(sn + 8192);
    float4* sk4  = (float4*)(sn + 16384);
    float*  wsym = sn + 24576;
    float*  wout = sn + 24896;
    float4* aggb = (float4*)(sn + 24960);
    float4* nfb  = (float4*)(sn + 24960 + 8192);
    float4* psb  = (float4*)(sn + 24960 + 16384);

    int tid = threadIdx.x;
    int sp = blockIdx.y;

    {
        const float2* ds2 = (const float2*)Wds;
        const float2* dv2 = (const float2*)Wdv;
        const float2* ls2 = (const float2*)WLs;
        const float2* lv2 = (const float2*)WLv;
        const float2* ss2 = (const float2*)(Wsk_s + (size_t)sp * 4096);
        const float2* sv2 = (const float2*)(Wsk_v + (size_t)sp * 4096);
        for (int i = tid; i < 2048; i += 256) {
            float2 a = ds2[i], b = dv2[i];
            wd4[i] = make_float4(a.x, b.x, a.y, b.y);
            float2 cl = ls2[i], dl = lv2[i];
            wl4[i] = make_float4(cl.x, dl.x, cl.y, dl.y);
            float2 e = ss2[i], f = sv2[i];
            sk4[i] = make_float4(e.x, f.x, e.y, f.y);
        }
        for (int i = tid; i < 192; i += 256) wsym[i] = wsym_s[sp * 192 + i];
        for (int i = tid; i < 128; i += 256) wsym[192 + i] = wsym_v[sp * 128 + i];
        if (tid < 64) wout[tid] = Wout[tid];
    }
    __syncthreads();

    int warp = tid >> 5, lane = tid & 31;
    float4* ab = aggb + warp * 256;
    float4* nb = nfb + warp * 256;
    float4* pb = psb + warp * 256;
    int cnt = g_cnt[sp];
    const int* lst = g_bkt + sp * NN;
    const float* ws0 = wsym, *ws1 = wsym + 64, *ws2 = wsym + 128;
    const float* wv0 = wsym + 192, *wv1 = wsym + 256;

    for (int base = blockIdx.x * 32 + warp * 4; base < cnt; base += gridDim.x * 32) {
        int nv = cnt - base; if (nv > 4) nv = 4;
        int nn[4];
        #pragma unroll
        for (int j = 0; j < 4; j++) nn[j] = lst[base + ((j < nv) ? j : 0)];

        #pragma unroll
        for (int j = 0; j < 4; j++) {
            int n = nn[j];
            const float4* ga = (const float4*)g_A + (size_t)n * 64;
            ab[j * 64 + 2 * lane]     = ga[lane];        // channel 2l
            ab[j * 64 + 2 * lane + 1] = ga[32 + lane];   // channel 2l+1
            float2 sv = *(const float2*)(nfs + (size_t)n * 64 + 2 * lane);
            const float2* vp = (const float2*)(nfv + (size_t)n * 192);
            float2 p0 = vp[lane * 3], p1 = vp[lane * 3 + 1], p2 = vp[lane * 3 + 2];
            nb[j * 64 + 2 * lane]     = make_float4(sv.x, p0.x, p0.y, p1.x);
            nb[j * 64 + 2 * lane + 1] = make_float4(sv.y, p1.y, p2.x, p2.y);
        }
        __syncwarp();

        float acc[4][8];
        #pragma unroll
        for (int j = 0; j < 4; j++)
            #pragma unroll
            for (int q = 0; q < 8; q++) acc[j][q] = 0.f;

        #pragma unroll 4
        for (int f = 0; f < 64; f++) {
            float4 wq = wd4[f * 32 + lane];
            #pragma unroll
            for (int j = 0; j < 4; j++) {
                float4 a = ab[j * 64 + f];
                acc[j][0] = fmaf(a.x, wq.x, acc[j][0]);
                acc[j][1] = fmaf(a.y, wq.y, acc[j][1]);
                acc[j][2] = fmaf(a.z, wq.y, acc[j][2]);
                acc[j][3] = fmaf(a.w, wq.y, acc[j][3]);
                acc[j][4] = fmaf(a.x, wq.z, acc[j][4]);
                acc[j][5] = fmaf(a.y, wq.w, acc[j][5]);
                acc[j][6] = fmaf(a.z, wq.w, acc[j][6]);
                acc[j][7] = fmaf(a.w, wq.w, acc[j][7]);
            }
        }

        int c0 = 2 * lane, c1 = 2 * lane + 1;
        #pragma unroll
        for (int j = 0; j < 4; j++) {
            float sa0 = acc[j][0] * 0.25f, va0 = acc[j][1] * 0.25f;
            float va1 = acc[j][2] * 0.25f, va2 = acc[j][3] * 0.25f;
            float sa1 = acc[j][4] * 0.25f, vb0 = acc[j][5] * 0.25f;
            float vb1 = acc[j][6] * 0.25f, vb2 = acc[j][7] * 0.25f;
            float ps0 = ws0[c0] * sa0 + ws1[c0] * sa0 * sa0
                      + ws2[c0] * (va0 * va0 + va1 * va1 + va2 * va2);
            float cc0 = wv0[c0] + wv1[c0] * sa0;
            float ps1 = ws0[c1] * sa1 + ws1[c1] * sa1 * sa1
                      + ws2[c1] * (vb0 * vb0 + vb1 * vb1 + vb2 * vb2);
            float cc1 = wv0[c1] + wv1[c1] * sa1;
            pb[j * 64 + c0] = make_float4(ps0, cc0 * va0, cc0 * va1, cc0 * va2);
            pb[j * 64 + c1] = make_float4(ps1, cc1 * vb0, cc1 * vb1, cc1 * vb2);
        }
        __syncwarp();

        float a2c[4][8];
        #pragma unroll
        for (int j = 0; j < 4; j++)
            #pragma unroll
            for (int q = 0; q < 8; q++) a2c[j][q] = 0.f;

        #pragma unroll 4
        for (int f = 0; f < 64; f++) {
            float4 wl = wl4[f * 32 + lane];
            float4 sk = sk4[f * 32 + lane];
            #pragma unroll
            for (int j = 0; j < 4; j++) {
                float4 p = pb[j * 64 + f];
                float4 q = nb[j * 64 + f];
                a2c[j][0] = fmaf(p.x, wl.x, fmaf(q.x, sk.x, a2c[j][0]));
                a2c[j][1] = fmaf(p.y, wl.y, fmaf(q.y, sk.y, a2c[j][1]));
                a2c[j][2] = fmaf(p.z, wl.y, fmaf(q.z, sk.y, a2c[j][2]));
                a2c[j][3] = fmaf(p.w, wl.y, fmaf(q.w, sk.y, a2c[j][3]));
                a2c[j][4] = fmaf(p.x, wl.z, fmaf(q.x, sk.z, a2c[j][4]));
                a2c[j][5] = fmaf(p.y, wl.w, fmaf(q.y, sk.w, a2c[j][5]));
                a2c[j][6] = fmaf(p.z, wl.w, fmaf(q.z, sk.w, a2c[j][6]));
                a2c[j][7] = fmaf(p.w, wl.w, fmaf(q.w, sk.w, a2c[j][7]));
            }
        }

        #pragma unroll
        for (int j = 0; j < 4; j++) {
            int n = nn[j];
            float r = a2c[j][0] * wout[c0] + a2c[j][4] * wout[c1];
            #pragma unroll
            for (int off = 16; off > 0; off >>= 1)
                r += __shfl_xor_sync(0xffffffffu, r, off);
            if (j < nv) {
                *(float2*)(fsO + (size_t)n * 64 + c0) = make_float2(a2c[j][0], a2c[j][4]);
                float* vb = fvO + (size_t)n * 192 + 6 * lane;
                *(float2*)(vb)     = make_float2(a2c[j][1], a2c[j][2]);
                *(float2*)(vb + 2) = make_float2(a2c[j][3], a2c[j][5]);
                *(float2*)(vb + 4) = make_float2(a2c[j][6], a2c[j][7]);
                if (lane == 0) out0[n] = r;
            }
        }
        __syncwarp();
    }
}

// ============================================================================
extern "C" void kernel_launch(void* const* d_in, const int* in_sizes, int n_in,
                              void* d_out, int out_size)
{
    const float* vectors  = (const float*)d_in[0];
    const float* nfs      = (const float*)d_in[1];
    const float* nfv      = (const float*)d_in[2];
    const float* RE       = (const float*)d_in[3];
    const float* Wus      = (const float*)d_in[4];
    const float* Wuv      = (const float*)d_in[5];
    const float* Wr1      = (const float*)d_in[6];
    const float* Wr2      = (const float*)d_in[7];
    const float* Wds      = (const float*)d_in[8];
    const float* Wdv      = (const float*)d_in[9];
    const float* wsym_s   = (const float*)d_in[10];
    const float* wsym_v   = (const float*)d_in[11];
    const float* WLs      = (const float*)d_in[12];
    const float* WLv      = (const float*)d_in[13];
    const float* Wsk_s    = (const float*)d_in[14];
    const float* Wsk_v    = (const float*)d_in[15];
    const float* Wout     = (const float*)d_in[16];
    const int*   specie   = (const int*)d_in[17];
    const int*   senders  = (const int*)d_in[18];
    const int*   receivers= (const int*)d_in[19];

    int N = in_sizes[1] / 64;
    int E = in_sizes[18];
    if (N > NN) N = NN;
    if (E > EE) E = EE;

    float* out0 = (float*)d_out;
    float* fsO  = out0 + N;
    float* fvO  = fsO + (size_t)N * 64;

    const int UP_SMEM   = (8192 + 2048 + 8192) * 4;                 // 73728 B
    const int EDGE_SMEM = 24448 * 4;                                // 97792 B
    const int NODE_SMEM = (24960 + 3 * 8192) * 4;                   // 198144 B
    cudaFuncSetAttribute(k_up,   cudaFuncAttributeMaxDynamicSharedMemorySize, UP_SMEM);
    cudaFuncSetAttribute(k_edge, cudaFuncAttributeMaxDynamicSharedMemorySize, EDGE_SMEM);
    cudaFuncSetAttribute(k_node, cudaFuncAttributeMaxDynamicSharedMemorySize, NODE_SMEM);

    // species bucketing
    k_zero_cnt<<<1, 32>>>();
    k_bucket<<<(N + 255) / 256, 256>>>(specie, N);

    k_up<<<296, 256, UP_SMEM>>>(nfs, nfv, Wus, Wuv, N);
    k_edge<<<296, 512, EDGE_SMEM>>>(RE, Wr1, Wr2, vectors, senders, receivers, E);
    k_node<<<dim3(15, NSPEC), 256, NODE_SMEM>>>(nfs, nfv, Wds, Wdv,
                                                wsym_s, wsym_v, WLs, WLv,
                                                Wsk_s, Wsk_v, Wout,
                                                out0, fsO, fvO);
}

// round 17
// speedup vs baseline: 1.6180x; 1.0191x over previous
#include <cuda_runtime.h>
#include <cuda_fp16.h>
#include <math.h>

#define NN 50000
#define EE 800000
#define NSPEC 10

// ---- scratch (static device globals; allocation-free) ----
__device__ float g_SV[NN * 256];        // packed fp32 up-projected feats [N][2][32][4]:
                                        //   block0[lane]=(s0,v0x,v0y,v0z)  (channel 2l)
                                        //   block1[lane]=(s1,v1x,v1y,v1z)  (channel 2l+1)
__device__ float g_A[NN * 256];         // aggregation [N][2][32][4]:
                                        //   block0 = channel 2l (s,vx,vy,vz), block1 = channel 2l+1
__device__ int   g_cnt[16];             // per-species node counts
__device__ int   g_bkt[NSPEC * NN];     // per-species node lists

// ============================================================================
// Species bucketing (warp-aggregated)
// ============================================================================
__global__ void k_zero_cnt() { if (threadIdx.x < 16) g_cnt[threadIdx.x] = 0; }

__global__ __launch_bounds__(256) void k_bucket(const int* __restrict__ specie, int N)
{
    int i = blockIdx.x * blockDim.x + threadIdx.x;
    if (i < N) {
        int sp = specie[i];
        unsigned mask = __match_any_sync(__activemask(), sp);
        int lane = threadIdx.x & 31;
        int leader = __ffs(mask) - 1;
        int rank = __popc(mask & ((1u << lane) - 1));
        int base = 0;
        if (lane == leader) base = atomicAdd(&g_cnt[sp], __popc(mask));
        base = __shfl_sync(mask, base, leader);
        g_bkt[sp * NN + base + rank] = i;
    }
}

// ============================================================================
// Kernel A: linear-up -> packed g_SV (split layout) + zero aggregation buffer.
// ============================================================================
__global__ __launch_bounds__(256) void k_up(
    const float* __restrict__ nfs, const float* __restrict__ nfv,
    const float* __restrict__ Wus, const float* __restrict__ Wuv, int N)
{
    extern __shared__ float su[];
    float4* wsv4 = (float4*)su;
    float*  s_in = su + 8192;
    float4* v_in = (float4*)(su + 8192 + 2048);

    int tid = threadIdx.x;
    const float2* us2 = (const float2*)Wus;
    const float2* uv2 = (const float2*)Wuv;
    for (int i = tid; i < 2048; i += 256) {
        float2 a = us2[i], b = uv2[i];
        wsv4[i] = make_float4(a.x, b.x, a.y, b.y);
    }
    __syncthreads();

    int warp = tid >> 5, lane = tid & 31;
    float*  ss = s_in + warp * 256;
    float4* vv = v_in + warp * 256;

    for (int base = blockIdx.x * 32 + warp * 4; base < N; base += gridDim.x * 32) {
        int nv = N - base; if (nv > 4) nv = 4;
        #pragma unroll
        for (int j = 0; j < 4; j++) {
            if (j < nv) {
                int n = base + j;
                float2 sv = *(const float2*)(nfs + (size_t)n * 64 + 2 * lane);
                ss[j * 64 + 2 * lane]     = sv.x;
                ss[j * 64 + 2 * lane + 1] = sv.y;
                const float2* vp = (const float2*)(nfv + (size_t)n * 192);
                float2 p0 = vp[lane * 3], p1 = vp[lane * 3 + 1], p2 = vp[lane * 3 + 2];
                vv[j * 64 + 2 * lane]     = make_float4(p0.x, p0.y, p1.x, 0.f);
                vv[j * 64 + 2 * lane + 1] = make_float4(p1.y, p2.x, p2.y, 0.f);
            }
        }
        __syncwarp();

        float acc[4][8];
        #pragma unroll
        for (int j = 0; j < 4; j++)
            #pragma unroll
            for (int q = 0; q < 8; q++) acc[j][q] = 0.f;

        #pragma unroll 4
        for (int f = 0; f < 64; f++) {
            float4 wq = wsv4[f * 32 + lane];
            #pragma unroll
            for (int j = 0; j < 4; j++) {
                float  sb = ss[j * 64 + f];
                float4 vb = vv[j * 64 + f];
                acc[j][0] = fmaf(sb, wq.x, acc[j][0]);
                acc[j][1] = fmaf(sb, wq.z, acc[j][1]);
                acc[j][2] = fmaf(vb.x, wq.y, acc[j][2]);
                acc[j][3] = fmaf(vb.y, wq.y, acc[j][3]);
                acc[j][4] = fmaf(vb.z, wq.y, acc[j][4]);
                acc[j][5] = fmaf(vb.x, wq.w, acc[j][5]);
                acc[j][6] = fmaf(vb.y, wq.w, acc[j][6]);
                acc[j][7] = fmaf(vb.z, wq.w, acc[j][7]);
            }
        }

        for (int j = 0; j < nv; j++) {
            int n = base + j;
            // split layout: block0 = channel 2l, block1 = channel 2l+1
            float4* gp = (float4*)(g_SV + (size_t)n * 256);
            gp[lane]      = make_float4(acc[j][0], acc[j][2], acc[j][3], acc[j][4]);
            gp[32 + lane] = make_float4(acc[j][1], acc[j][5], acc[j][6], acc[j][7]);
            float4* za = (float4*)(g_A + (size_t)n * 256);
            za[lane]      = make_float4(0.f, 0.f, 0.f, 0.f);
            za[32 + lane] = make_float4(0.f, 0.f, 0.f, 0.f);
        }
        __syncwarp();
    }
}

// ============================================================================
// Kernel B (warp-specialized pipeline, fp16 MMA): 512 threads, 2 blocks/SM.
//   warps 0-7  (producers): edge-info + radial MLP (fp16 MMA) tile t -> smem[p]
//   warps 8-15 (consumers): messages + atomic scatter tile t-1 from smem[1-p]
// Both the sender gather and the aggregation REDs use split [2][32][4]
// layouts: every 16B vector op spans a contiguous 512B across the warp
// -> 4 L1 wavefronts per instruction instead of 8.
// ============================================================================
__global__ __launch_bounds__(512, 2) void k_edge(
    const float* __restrict__ RE, const float* __restrict__ Wr1,
    const float* __restrict__ Wr2, const float* __restrict__ vectors,
    const int* __restrict__ senders, const int* __restrict__ receivers, int En)
{
    extern __shared__ float sg[];
    __half* wr2t = (__half*)sg;                     // [320][72] halfs -> 11520 floats
    __half* csmH = (__half*)(sg + 11520);           // 2 * 32*328 halfs -> 10496 floats
    __half* hu   = (__half*)(sg + 22016);           // [32][72] halfs -> 1152 floats
    float*  res  = sg + 23168;                      // 256
    float*  wr1s = sg + 23424;                      // 512
    float*  einf = sg + 23936;                      // 2 * 32 * 8 = 512
    // total 24448 floats = 97792 B

    int tid = threadIdx.x;
    // stage W_r2 transposed: wr2t[n][j] = Wr2[j][n]
    for (int i = tid; i < 20480; i += 512) {
        int j = i / 320, n = i - j * 320;
        wr2t[n * 72 + j] = __float2half_rn(Wr2[i]);
    }
    for (int i = tid; i < 512; i += 512) wr1s[i] = Wr1[i];
    __syncthreads();

    int lane = tid & 31, warp = tid >> 5;
    int gid = lane >> 2, tig = lane & 3;
    bool producer = (warp < 8);
    int ntiles = (En + 31) >> 5;
    int gd = gridDim.x;
    int p = 0;

    for (int it = 0; ; it++) {
        int tP = blockIdx.x + it * gd;
        int tC = tP - gd;
        if (tC >= ntiles) break;
        __half* bufP = csmH + p * 10496;
        __half* bufC = csmH + (1 - p) * 10496;

        if (producer && tP < ntiles) {
            int e0 = tP << 5;
            // stage RE tile + per-edge info (Y, s, r)
            {
                int el = tid >> 3;
                int e = e0 + el;
                res[tid] = (e < En) ? __ldg(RE + (size_t)e * 8 + (tid & 7)) : 0.f;
                if (tid < 32) {
                    int ee = e0 + tid;
                    float* ei = einf + p * 256 + tid * 8;
                    if (ee < En) {
                        float vx = __ldg(vectors + (size_t)ee * 3 + 0);
                        float vy = __ldg(vectors + (size_t)ee * 3 + 1);
                        float vz = __ldg(vectors + (size_t)ee * 3 + 2);
                        float ri = 1.f / (sqrtf(vx * vx + vy * vy + vz * vz) + 1e-9f);
                        ei[0] = vx * ri; ei[1] = vy * ri; ei[2] = vz * ri;
                        ei[3] = __int_as_float(__ldg(senders + ee));
                        ei[4] = __int_as_float(__ldg(receivers + ee));
                    }
                }
            }
            asm volatile("bar.sync 1, 256;" ::: "memory");
            // h = silu(res @ W_r1), two adjacent j per thread -> half2 store
            #pragma unroll
            for (int i = 0; i < 4; i++) {
                int idx = tid + 256 * i;        // 0..1023
                int e = idx >> 5;               // 0..31
                int j = (idx & 31) * 2;         // 0..62 even
                const float* rr = res + e * 8;
                float a0 = 0.f, a1 = 0.f;
                #pragma unroll
                for (int k = 0; k < 8; k++) {
                    float r = rr[k];
                    a0 = fmaf(r, wr1s[k * 64 + j], a0);
                    a1 = fmaf(r, wr1s[k * 64 + j + 1], a1);
                }
                float h0 = __fdividef(a0, 1.f + __expf(-a0));
                float h1 = __fdividef(a1, 1.f + __expf(-a1));
                *(half2*)(hu + e * 72 + j) = __floats2half2_rn(h0, h1);
            }
            asm volatile("bar.sync 1, 256;" ::: "memory");

            // MMA: C[32,320] = h @ W_r2 (fp16 in, fp32 accum), warp = 40-col strip
            float c[2][5][4];
            #pragma unroll
            for (int mt = 0; mt < 2; mt++)
                #pragma unroll
                for (int nt = 0; nt < 5; nt++)
                    #pragma unroll
                    for (int q = 0; q < 4; q++) c[mt][nt][q] = 0.f;

            #pragma unroll
            for (int ks = 0; ks < 4; ks++) {
                int kb = ks * 16;
                unsigned a[2][4];
                #pragma unroll
                for (int mt = 0; mt < 2; mt++) {
                    int r0 = mt * 16 + gid;
                    a[mt][0] = *(const unsigned*)(hu + r0 * 72 + kb + 2 * tig);
                    a[mt][1] = *(const unsigned*)(hu + (r0 + 8) * 72 + kb + 2 * tig);
                    a[mt][2] = *(const unsigned*)(hu + r0 * 72 + kb + 2 * tig + 8);
                    a[mt][3] = *(const unsigned*)(hu + (r0 + 8) * 72 + kb + 2 * tig + 8);
                }
                #pragma unroll
                for (int nt = 0; nt < 5; nt++) {
                    int col = warp * 40 + nt * 8 + gid;
                    unsigned b0 = *(const unsigned*)(wr2t + col * 72 + kb + 2 * tig);
                    unsigned b1 = *(const unsigned*)(wr2t + col * 72 + kb + 2 * tig + 8);
                    #pragma unroll
                    for (int mt = 0; mt < 2; mt++) {
                        asm volatile(
                            "mma.sync.aligned.m16n8k16.row.col.f32.f16.f16.f32 "
                            "{%0,%1,%2,%3}, {%4,%5,%6,%7}, {%8,%9}, {%0,%1,%2,%3};\n"
                            : "+f"(c[mt][nt][0]), "+f"(c[mt][nt][1]),
                              "+f"(c[mt][nt][2]), "+f"(c[mt][nt][3])
                            : "r"(a[mt][0]), "r"(a[mt][1]), "r"(a[mt][2]), "r"(a[mt][3]),
                              "r"(b0), "r"(b1));
                    }
                }
            }
            // store C fragments into bufP as fp16
            #pragma unroll
            for (int mt = 0; mt < 2; mt++) {
                int r0 = mt * 16 + gid;
                #pragma unroll
                for (int nt = 0; nt < 5; nt++) {
                    int col = warp * 40 + nt * 8 + 2 * tig;
                    *(half2*)(bufP + r0 * 328 + col) =
                        __floats2half2_rn(c[mt][nt][0], c[mt][nt][1]);
                    *(half2*)(bufP + (r0 + 8) * 328 + col) =
                        __floats2half2_rn(c[mt][nt][2], c[mt][nt][3]);
                }
            }
        }

        if (!producer && tC >= 0) {
            int e0 = tC << 5;
            int cw = warp - 8;
            const float* einfC = einf + (1 - p) * 256;
            #pragma unroll
            for (int i = 0; i < 4; i++) {
                int el = cw * 4 + i;
                int e = e0 + el;
                if (e < En) {
                    const __half* cwp = bufC + el * 328;
                    float2 w0 = __half22float2(*(const half2*)(cwp + 2 * lane));
                    float2 w1 = __half22float2(*(const half2*)(cwp + 64 + 2 * lane));
                    float2 w2 = __half22float2(*(const half2*)(cwp + 128 + 2 * lane));
                    float2 w3 = __half22float2(*(const half2*)(cwp + 192 + 2 * lane));
                    float2 w4 = __half22float2(*(const half2*)(cwp + 256 + 2 * lane));

                    const float* ei = einfC + el * 8;
                    float Y0 = ei[0], Y1 = ei[1], Y2 = ei[2];
                    int s = __float_as_int(ei[3]);
                    int r = __float_as_int(ei[4]);

                    // split-layout gather: two contiguous-512B LDG.128
                    const float4* gp = (const float4*)(g_SV + (size_t)s * 256);
                    float4 q1 = __ldg(gp + lane);        // (s0, v0x, v0y, v0z)
                    float4 q2 = __ldg(gp + 32 + lane);   // (s1, v1x, v1y, v1z)
                    float xs0 = q1.x, xs1 = q2.x;
                    float a0 = q1.y, a1 = q1.z, a2 = q1.w;
                    float b0 = q2.y, b1 = q2.z, b2 = q2.w;

                    float dota = a0 * Y0 + a1 * Y1 + a2 * Y2;
                    float dotb = b0 * Y0 + b1 * Y1 + b2 * Y2;

                    float msa = w0.x * xs0 + w3.x * dota;
                    float msb = w0.y * xs1 + w3.y * dotb;

                    float cxa0 = a1 * Y2 - a2 * Y1;
                    float cxa1 = a2 * Y0 - a0 * Y2;
                    float cxa2 = a0 * Y1 - a1 * Y0;
                    float cxb0 = b1 * Y2 - b2 * Y1;
                    float cxb1 = b2 * Y0 - b0 * Y2;
                    float cxb2 = b0 * Y1 - b1 * Y0;

                    float sa = w1.x * xs0, sb = w1.y * xs1;
                    float mva0 = sa * Y0 + w2.x * a0 + w4.x * cxa0;
                    float mva1 = sa * Y1 + w2.x * a1 + w4.x * cxa1;
                    float mva2 = sa * Y2 + w2.x * a2 + w4.x * cxa2;
                    float mvb0 = sb * Y0 + w2.y * b0 + w4.y * cxb0;
                    float mvb1 = sb * Y1 + w2.y * b1 + w4.y * cxb1;
                    float mvb2 = sb * Y2 + w2.y * b2 + w4.y * cxb2;

                    // split layout: channel-2l block then channel-2l+1 block,
                    // each red.v4 spans a contiguous 512B across the warp
                    float* baseA = g_A + (size_t)r * 256 + lane * 4;
                    asm volatile("red.global.add.v4.f32 [%0], {%1,%2,%3,%4};"
                                 :: "l"(baseA), "f"(msa), "f"(mva0), "f"(mva1), "f"(mva2)
                                 : "memory");
                    asm volatile("red.global.add.v4.f32 [%0], {%1,%2,%3,%4};"
                                 :: "l"(baseA + 128), "f"(msb), "f"(mvb0), "f"(mvb1), "f"(mvb2)
                                 : "memory");
                }
            }
        }
        __syncthreads();
        p ^= 1;
    }
}

// ============================================================================
// Kernel C: node post. Blocks own ONE species (skip weights staged in smem).
// Reads g_A in the split [2][32][4] layout.
// ============================================================================
__global__ __launch_bounds__(256) void k_node(
    const float* __restrict__ nfs, const float* __restrict__ nfv,
    const float* __restrict__ Wds, const float* __restrict__ Wdv,
    const float* __restrict__ wsym_s, const float* __restrict__ wsym_v,
    const float* __restrict__ WLs, const float* __restrict__ WLv,
    const float* __restrict__ Wsk_s, const float* __restrict__ Wsk_v,
    const float* __restrict__ Wout,
    float* __restrict__ out0, float* __restrict__ fsO, float* __restrict__ fvO)
{
    extern __shared__ float sn[];
    float4* wd4  = (float4*)sn;
    float4* wl4  = (float4*)(sn + 8192);
    float4* sk4  = (float4*)(sn + 16384);
    float*  wsym = sn + 24576;
    float*  wout = sn + 24896;
    float4* aggb = (float4*)(sn + 24960);
    float4* nfb  = (float4*)(sn + 24960 + 8192);
    float4* psb  = (float4*)(sn + 24960 + 16384);

    int tid = threadIdx.x;
    int sp = blockIdx.y;

    {
        const float2* ds2 = (const float2*)Wds;
        const float2* dv2 = (const float2*)Wdv;
        const float2* ls2 = (const float2*)WLs;
        const float2* lv2 = (const float2*)WLv;
        const float2* ss2 = (const float2*)(Wsk_s + (size_t)sp * 4096);
        const float2* sv2 = (const float2*)(Wsk_v + (size_t)sp * 4096);
        for (int i = tid; i < 2048; i += 256) {
            float2 a = ds2[i], b = dv2[i];
            wd4[i] = make_float4(a.x, b.x, a.y, b.y);
            float2 cl = ls2[i], dl = lv2[i];
            wl4[i] = make_float4(cl.x, dl.x, cl.y, dl.y);
            float2 e = ss2[i], f = sv2[i];
            sk4[i] = make_float4(e.x, f.x, e.y, f.y);
        }
        for (int i = tid; i < 192; i += 256) wsym[i] = wsym_s[sp * 192 + i];
        for (int i = tid; i < 128; i += 256) wsym[192 + i] = wsym_v[sp * 128 + i];
        if (tid < 64) wout[tid] = Wout[tid];
    }
    __syncthreads();

    int warp = tid >> 5, lane = tid & 31;
    float4* ab = aggb + warp * 256;
    float4* nb = nfb + warp * 256;
    float4* pb = psb + warp * 256;
    int cnt = g_cnt[sp];
    const int* lst = g_bkt + sp * NN;
    const float* ws0 = wsym, *ws1 = wsym + 64, *ws2 = wsym + 128;
    const float* wv0 = wsym + 192, *wv1 = wsym + 256;

    for (int base = blockIdx.x * 32 + warp * 4; base < cnt; base += gridDim.x * 32) {
        int nv = cnt - base; if (nv > 4) nv = 4;
        int nn[4];
        #pragma unroll
        for (int j = 0; j < 4; j++) nn[j] = lst[base + ((j < nv) ? j : 0)];

        #pragma unroll
        for (int j = 0; j < 4; j++) {
            int n = nn[j];
            const float4* ga = (const float4*)g_A + (size_t)n * 64;
            ab[j * 64 + 2 * lane]     = ga[lane];        // channel 2l
            ab[j * 64 + 2 * lane + 1] = ga[32 + lane];   // channel 2l+1
            float2 sv = *(const float2*)(nfs + (size_t)n * 64 + 2 * lane);
            const float2* vp = (const float2*)(nfv + (size_t)n * 192);
            float2 p0 = vp[lane * 3], p1 = vp[lane * 3 + 1], p2 = vp[lane * 3 + 2];
            nb[j * 64 + 2 * lane]     = make_float4(sv.x, p0.x, p0.y, p1.x);
            nb[j * 64 + 2 * lane + 1] = make_float4(sv.y, p1.y, p2.x, p2.y);
        }
        __syncwarp();

        float acc[4][8];
        #pragma unroll
        for (int j = 0; j < 4; j++)
            #pragma unroll
            for (int q = 0; q < 8; q++) acc[j][q] = 0.f;

        #pragma unroll 4
        for (int f = 0; f < 64; f++) {
            float4 wq = wd4[f * 32 + lane];
            #pragma unroll
            for (int j = 0; j < 4; j++) {
                float4 a = ab[j * 64 + f];
                acc[j][0] = fmaf(a.x, wq.x, acc[j][0]);
                acc[j][1] = fmaf(a.y, wq.y, acc[j][1]);
                acc[j][2] = fmaf(a.z, wq.y, acc[j][2]);
                acc[j][3] = fmaf(a.w, wq.y, acc[j][3]);
                acc[j][4] = fmaf(a.x, wq.z, acc[j][4]);
                acc[j][5] = fmaf(a.y, wq.w, acc[j][5]);
                acc[j][6] = fmaf(a.z, wq.w, acc[j][6]);
                acc[j][7] = fmaf(a.w, wq.w, acc[j][7]);
            }
        }

        int c0 = 2 * lane, c1 = 2 * lane + 1;
        #pragma unroll
        for (int j = 0; j < 4; j++) {
            float sa0 = acc[j][0] * 0.25f, va0 = acc[j][1] * 0.25f;
            float va1 = acc[j][2] * 0.25f, va2 = acc[j][3] * 0.25f;
            float sa1 = acc[j][4] * 0.25f, vb0 = acc[j][5] * 0.25f;
            float vb1 = acc[j][6] * 0.25f, vb2 = acc[j][7] * 0.25f;
            float ps0 = ws0[c0] * sa0 + ws1[c0] * sa0 * sa0
                      + ws2[c0] * (va0 * va0 + va1 * va1 + va2 * va2);
            float cc0 = wv0[c0] + wv1[c0] * sa0;
            float ps1 = ws0[c1] * sa1 + ws1[c1] * sa1 * sa1
                      + ws2[c1] * (vb0 * vb0 + vb1 * vb1 + vb2 * vb2);
            float cc1 = wv0[c1] + wv1[c1] * sa1;
            pb[j * 64 + c0] = make_float4(ps0, cc0 * va0, cc0 * va1, cc0 * va2);
            pb[j * 64 + c1] = make_float4(ps1, cc1 * vb0, cc1 * vb1, cc1 * vb2);
        }
        __syncwarp();

        float a2c[4][8];
        #pragma unroll
        for (int j = 0; j < 4; j++)
            #pragma unroll
            for (int q = 0; q < 8; q++) a2c[j][q] = 0.f;

        #pragma unroll 4
        for (int f = 0; f < 64; f++) {
            float4 wl = wl4[f * 32 + lane];
            float4 sk = sk4[f * 32 + lane];
            #pragma unroll
            for (int j = 0; j < 4; j++) {
                float4 p = pb[j * 64 + f];
                float4 q = nb[j * 64 + f];
                a2c[j][0] = fmaf(p.x, wl.x, fmaf(q.x, sk.x, a2c[j][0]));
                a2c[j][1] = fmaf(p.y, wl.y, fmaf(q.y, sk.y, a2c[j][1]));
                a2c[j][2] = fmaf(p.z, wl.y, fmaf(q.z, sk.y, a2c[j][2]));
                a2c[j][3] = fmaf(p.w, wl.y, fmaf(q.w, sk.y, a2c[j][3]));
                a2c[j][4] = fmaf(p.x, wl.z, fmaf(q.x, sk.z, a2c[j][4]));
                a2c[j][5] = fmaf(p.y, wl.w, fmaf(q.y, sk.w, a2c[j][5]));
                a2c[j][6] = fmaf(p.z, wl.w, fmaf(q.z, sk.w, a2c[j][6]));
                a2c[j][7] = fmaf(p.w, wl.w, fmaf(q.w, sk.w, a2c[j][7]));
            }
        }

        #pragma unroll
        for (int j = 0; j < 4; j++) {
            int n = nn[j];
            float r = a2c[j][0] * wout[c0] + a2c[j][4] * wout[c1];
            #pragma unroll
            for (int off = 16; off > 0; off >>= 1)
                r += __shfl_xor_sync(0xffffffffu, r, off);
            if (j < nv) {
                *(float2*)(fsO + (size_t)n * 64 + c0) = make_float2(a2c[j][0], a2c[j][4]);
                float* vb = fvO + (size_t)n * 192 + 6 * lane;
                *(float2*)(vb)     = make_float2(a2c[j][1], a2c[j][2]);
                *(float2*)(vb + 2) = make_float2(a2c[j][3], a2c[j][5]);
                *(float2*)(vb + 4) = make_float2(a2c[j][6], a2c[j][7]);
                if (lane == 0) out0[n] = r;
            }
        }
        __syncwarp();
    }
}

// ============================================================================
extern "C" void kernel_launch(void* const* d_in, const int* in_sizes, int n_in,
                              void* d_out, int out_size)
{
    const float* vectors  = (const float*)d_in[0];
    const float* nfs      = (const float*)d_in[1];
    const float* nfv      = (const float*)d_in[2];
    const float* RE       = (const float*)d_in[3];
    const float* Wus      = (const float*)d_in[4];
    const float* Wuv      = (const float*)d_in[5];
    const float* Wr1      = (const float*)d_in[6];
    const float* Wr2      = (const float*)d_in[7];
    const float* Wds      = (const float*)d_in[8];
    const float* Wdv      = (const float*)d_in[9];
    const float* wsym_s   = (const float*)d_in[10];
    const float* wsym_v   = (const float*)d_in[11];
    const float* WLs      = (const float*)d_in[12];
    const float* WLv      = (const float*)d_in[13];
    const float* Wsk_s    = (const float*)d_in[14];
    const float* Wsk_v    = (const float*)d_in[15];
    const float* Wout     = (const float*)d_in[16];
    const int*   specie   = (const int*)d_in[17];
    const int*   senders  = (const int*)d_in[18];
    const int*   receivers= (const int*)d_in[19];

    int N = in_sizes[1] / 64;
    int E = in_sizes[18];
    if (N > NN) N = NN;
    if (E > EE) E = EE;

    float* out0 = (float*)d_out;
    float* fsO  = out0 + N;
    float* fvO  = fsO + (size_t)N * 64;

    const int UP_SMEM   = (8192 + 2048 + 8192) * 4;                 // 73728 B
    const int EDGE_SMEM = 24448 * 4;                                // 97792 B
    const int NODE_SMEM = (24960 + 3 * 8192) * 4;                   // 198144 B
    cudaFuncSetAttribute(k_up,   cudaFuncAttributeMaxDynamicSharedMemorySize, UP_SMEM);
    cudaFuncSetAttribute(k_edge, cudaFuncAttributeMaxDynamicSharedMemorySize, EDGE_SMEM);
    cudaFuncSetAttribute(k_node, cudaFuncAttributeMaxDynamicSharedMemorySize, NODE_SMEM);

    // species bucketing
    k_zero_cnt<<<1, 32>>>();
    k_bucket<<<(N + 255) / 256, 256>>>(specie, N);

    k_up<<<296, 256, UP_SMEM>>>(nfs, nfv, Wus, Wuv, N);
    k_edge<<<296, 512, EDGE_SMEM>>>(RE, Wr1, Wr2, vectors, senders, receivers, E);
    k_node<<<dim3(15, NSPEC), 256, NODE_SMEM>>>(nfs, nfv, Wds, Wdv,
                                                wsym_s, wsym_v, WLs, WLv,
                                                Wsk_s, Wsk_v, Wout,
                                                out0, fsO, fvO);
}